// round 1
// baseline (speedup 1.0000x reference)
#include <cuda_runtime.h>

// CRF loss forward kernel for B=512, N=1024, K=64 on sm_100a.
// Linear-domain forward scan with register-resident exp(trans) and f32x2 FMAs.

typedef unsigned long long ull;
#define FULLMASK 0xffffffffu

__device__ __forceinline__ void fma2(ull &d, ull a, ull b) {
    asm("fma.rn.f32x2 %0, %1, %2, %0;" : "+l"(d) : "l"(a), "l"(b));
}
__device__ __forceinline__ ull pack2(float x, float y) {
    ull r; asm("mov.b64 %0, {%1, %2};" : "=l"(r) : "f"(x), "f"(y)); return r;
}
__device__ __forceinline__ void unpack2(ull v, float &x, float &y) {
    asm("mov.b64 {%0, %1}, %2;" : "=f"(x), "=f"(y) : "l"(v));
}
__device__ __forceinline__ float ex2f(float x) {
    float r; asm("ex2.approx.f32 %0, %1;" : "=f"(r) : "f"(x)); return r;
}
__device__ __forceinline__ float lg2f(float x) {
    float r; asm("lg2.approx.f32 %0, %1;" : "=f"(r) : "f"(x)); return r;
}

__global__ __launch_bounds__(32) void crf_fwd_kernel(
    const float* __restrict__ y_pred,   // [B, N, K]
    const float* __restrict__ trans,    // [K, K]
    const int*   __restrict__ y_true,   // [B, N]
    float*       __restrict__ out)      // [B]
{
    constexpr int N = 1024;
    constexpr int K = 64;
    constexpr float LOG2E = 1.4426950408889634f;

    const int b    = blockIdx.x;
    const int lane = threadIdx.x;

    __shared__ float sh_trans[K * K];   // raw trans, 16 KB
    __shared__ ull   sh_a[32];          // alpha state: 64 floats as 32 pairs

    // ---- stage trans into shared (coalesced) ----
    {
        const float4* tg = (const float4*)trans;
        float4* sg = (float4*)sh_trans;
        #pragma unroll
        for (int i = 0; i < (K * K / 4) / 32; i++)
            sg[lane + i * 32] = tg[lane + i * 32];
    }
    __syncwarp();

    // ---- preload E = exp(trans) into registers, paired over i, for this lane's j0/j1 ----
    const int j0 = 2 * lane, j1 = j0 + 1;
    ull Er0[32], Er1[32];
    #pragma unroll
    for (int i2 = 0; i2 < 32; i2++) {
        float t00 = sh_trans[(2 * i2)     * K + j0];
        float t01 = sh_trans[(2 * i2 + 1) * K + j0];
        float t10 = sh_trans[(2 * i2)     * K + j1];
        float t11 = sh_trans[(2 * i2 + 1) * K + j1];
        Er0[i2] = pack2(ex2f(t00 * LOG2E), ex2f(t01 * LOG2E));
        Er1[i2] = pack2(ex2f(t10 * LOG2E), ex2f(t11 * LOG2E));
    }

    const float2* emrow = (const float2*)y_pred + (size_t)b * N * 32;
    const int*    ytrow = y_true + (size_t)b * N;

    // ---- t = 0 init ----
    float pt = 0.f, tv = 0.f;
    double c2;
    int ytprev;
    bool pm;
    {
        float2 v = emrow[lane];              // t=0, this lane's 2 channels
        bool okl = (v.x > -1e6f) & (v.y > -1e6f);
        bool ok0 = __all_sync(FULLMASK, okl);
        float mv0 = ok0 ? v.x : 0.f;
        float mv1 = ok0 ? v.y : 0.f;
        float mx = fmaxf(mv0, mv1);
        #pragma unroll
        for (int o = 16; o; o >>= 1) mx = fmaxf(mx, __shfl_xor_sync(FULLMASK, mx, o));
        float a0 = ex2f((mv0 - mx) * LOG2E);
        float a1 = ex2f((mv1 - mx) * LOG2E);
        c2 = (double)mx * 1.4426950408889634;   // carried scale in log2 units
        ytprev = ytrow[0];
        if (ok0) {
            if (ytprev == j0) pt += v.x;
            if (ytprev == j1) pt += v.y;
        }
        pm = ok0;
        sh_a[lane] = pack2(a0, a1);
    }
    __syncwarp();

    // ---- prefetch ring: 4 steps ahead ----
    float2 rem[4]; int ryt[4];
    #pragma unroll
    for (int k = 0; k < 4; k++) {
        rem[k] = __ldcs(&emrow[(1 + k) * 32 + lane]);
        ryt[k] = ytrow[1 + k];
    }

    const ulonglong2* sha2 = (const ulonglong2*)sh_a;

    for (int g = 0; g < 256; g++) {
        #pragma unroll
        for (int k = 0; k < 4; k++) {
            const int t = 1 + g * 4 + k;
            float2 em = rem[k];
            int    yt = ryt[k];
            int tn = t + 4; tn = (tn > N - 1) ? (N - 1) : tn;
            rem[k] = __ldcs(&emrow[tn * 32 + lane]);
            ryt[k] = ytrow[tn];

            if (t < N) {
                bool okl = (em.x > -1e6f) & (em.y > -1e6f);
                bool ok  = __all_sync(FULLMASK, okl);   // warp-uniform
                if (ok) {
                    // s[j] = sum_i a[i] * E[i][j], pairs over i via f32x2
                    ull acc0a = 0ull, acc0b = 0ull, acc1a = 0ull, acc1b = 0ull;
                    #pragma unroll
                    for (int p = 0; p < 16; p++) {
                        ulonglong2 ap = sha2[p];
                        fma2(acc0a, ap.x, Er0[2 * p]);
                        fma2(acc1a, ap.x, Er1[2 * p]);
                        fma2(acc0b, ap.y, Er0[2 * p + 1]);
                        fma2(acc1b, ap.y, Er1[2 * p + 1]);
                    }
                    float xa, ya, xb, yb, xc, yc, xd, yd;
                    unpack2(acc0a, xa, ya); unpack2(acc0b, xb, yb);
                    unpack2(acc1a, xc, yc); unpack2(acc1b, xd, yd);
                    float s0 = (xa + xb) + (ya + yb);
                    float s1 = (xc + xd) + (yc + yd);
                    s0 *= ex2f(em.x * LOG2E);
                    s1 *= ex2f(em.y * LOG2E);

                    // target-score gathers (emit row is L1-hot; trans in shared)
                    if (yt == j0) pt += em.x;
                    if (yt == j1) pt += em.y;
                    float trv = sh_trans[ytprev * K + yt];   // uniform addr, broadcast
                    if (pm && lane == 0) tv += trv;

                    // renormalize every 4 steps
                    if (k == 3) {
                        float r = fmaxf(s0, s1);
                        #pragma unroll
                        for (int o = 16; o; o >>= 1)
                            r = fmaxf(r, __shfl_xor_sync(FULLMASK, r, o));
                        float inv = 1.0f / r;
                        s0 *= inv; s1 *= inv;
                        c2 += (double)lg2f(r);
                    }
                    sh_a[lane] = pack2(s0, s1);
                    pm = true;
                } else {
                    pm = false;   // alpha unchanged, no score contributions
                }
                ytprev = yt;
                __syncwarp();
            }
        }
    }

    // ---- final: log_norm - target_score ----
    float ax, ay;
    unpack2(sh_a[lane], ax, ay);
    float ssum = ax + ay;
    #pragma unroll
    for (int o = 16; o; o >>= 1) ssum += __shfl_xor_sync(FULLMASK, ssum, o);
    #pragma unroll
    for (int o = 16; o; o >>= 1) pt   += __shfl_xor_sync(FULLMASK, pt, o);

    if (lane == 0) {
        double lognorm = (c2 + (double)lg2f(ssum)) * 0.6931471805599453;
        out[b] = (float)(lognorm - (double)(pt + tv));
    }
}

extern "C" void kernel_launch(void* const* d_in, const int* in_sizes, int n_in,
                              void* d_out, int out_size) {
    const float* y_pred = (const float*)d_in[0];
    const float* trans  = (const float*)d_in[1];
    const int*   y_true = (const int*)d_in[2];
    float* out = (float*)d_out;

    const int B = in_sizes[2] / 1024;   // 512
    crf_fwd_kernel<<<B, 32>>>(y_pred, trans, y_true, out);
}